// round 1
// baseline (speedup 1.0000x reference)
#include <cuda_runtime.h>

// Problem constants
constexpr int NBATCH = 4;
constexpr int CCH    = 256;
constexpr int HIMG   = 32;
constexpr int WIMG   = 32;
constexpr int HWPIX  = HIMG * WIMG;     // 1024
constexpr int NHEAD  = 2;
constexpr int HDIM   = 128;
constexpr int MAXD   = 7;
constexpr int WSIDE  = 15;
constexpr int WWIN   = 225;

// Scratch (device globals -- no cudaMalloc allowed)
__device__ float g_qproj[NBATCH * CCH * HWPIX];
__device__ float g_kproj[NBATCH * CCH * HWPIX];
__device__ float g_vproj[NBATCH * CCH * HWPIX];
__device__ float g_agg[HWPIX * NBATCH * CCH];

// ---------------------------------------------------------------------------
// Projection kernel: out[n,d,hw] = sum_c in[n,c,hw] * W[d,c] + b[d]
// One block = (proj p, batch n, 32-pixel tile). 256 threads, thread d = tid.
// ---------------------------------------------------------------------------
__global__ void proj_kernel(const float* __restrict__ q, const float* __restrict__ k,
                            const float* __restrict__ v,
                            const float* __restrict__ Wq, const float* __restrict__ bq,
                            const float* __restrict__ Wk, const float* __restrict__ bk,
                            const float* __restrict__ Wv, const float* __restrict__ bv) {
    __shared__ float xs[256][36];   // padded to 36 to break bank conflicts

    const int p   = blockIdx.z;
    const int n   = blockIdx.y;
    const int hw0 = blockIdx.x * 32;
    const int tid = threadIdx.x;

    const float *X, *Wm, *B;
    float* Y;
    if (p == 0)      { X = q; Wm = Wq; B = bq; Y = g_qproj; }
    else if (p == 1) { X = k; Wm = Wk; B = bk; Y = g_kproj; }
    else             { X = v; Wm = Wv; B = bv; Y = g_vproj; }

    // load X tile [256 c][32 hw], coalesced
    for (int idx = tid; idx < 256 * 32; idx += 256) {
        int c = idx >> 5, j = idx & 31;
        xs[c][j] = X[(n * 256 + c) * 1024 + hw0 + j];
    }
    __syncthreads();

    const int d = tid;
    float4 acc[8];
    {
        float bv_ = B[d];
        #pragma unroll
        for (int j = 0; j < 8; j++) acc[j] = make_float4(bv_, bv_, bv_, bv_);
    }
    const float* wrow = Wm + d * 256;
    #pragma unroll 4
    for (int c = 0; c < 256; c++) {
        float wv = wrow[c];
        const float4* xr = (const float4*)xs[c];
        #pragma unroll
        for (int j = 0; j < 8; j++) {
            float4 xv = xr[j];
            acc[j].x += wv * xv.x; acc[j].y += wv * xv.y;
            acc[j].z += wv * xv.z; acc[j].w += wv * xv.w;
        }
    }
    __syncthreads();
    // transpose through smem for coalesced global store
    {
        float4* row = (float4*)xs[d];
        #pragma unroll
        for (int j = 0; j < 8; j++) row[j] = acc[j];
    }
    __syncthreads();
    for (int idx = tid; idx < 256 * 32; idx += 256) {
        int dd = idx >> 5, j = idx & 31;
        Y[(n * 256 + dd) * 1024 + hw0 + j] = xs[dd][j];
    }
}

// ---------------------------------------------------------------------------
// Attention kernel: one block per (n, g, image row y). 256 threads.
// ---------------------------------------------------------------------------
constexpr int SM_Q    = 128 * 32;            // q tile  [c][x]
constexpr int SM_KV   = 128 * 48;            // padded k/v slab [c][px 0..45] (+2 pad)
constexpr int SM_AUX  = 2048;                // wrel [15][128]  OR vbias [128][16]
constexpr int SM_QK   = 225 * 32;            // logits / attn [wpos][x]
constexpr int SM_RED  = 8 * 32;              // softmax partials
constexpr int ATTN_SMEM_FLOATS = SM_Q + SM_KV + SM_AUX + SM_QK + SM_RED;
constexpr int ATTN_SMEM_BYTES  = ATTN_SMEM_FLOATS * 4;   // 78976 B

__global__ void attn_kernel(const float* __restrict__ Wrel,
                            const float* __restrict__ brel,
                            const float* __restrict__ Vbias) {
    extern __shared__ float sm[];
    float* q_s   = sm;
    float* kv_s  = q_s + SM_Q;
    float* aux_s = kv_s + SM_KV;
    float* qk_s  = aux_s + SM_AUX;
    float* red_s = qk_s + SM_QK;

    const int y = blockIdx.x, g = blockIdx.y, n = blockIdx.z;
    const int tid = threadIdx.x;
    const float invT = 0.08838834764831845f;   // 1/sqrt(128)

    const float* qbase = g_qproj + ((n * 2 + g) * 128) * 1024;
    const float* kbase = g_kproj + ((n * 2 + g) * 128) * 1024;
    const float* vbase = g_vproj + ((n * 2 + g) * 128) * 1024;
    const float* wrelg = Wrel + g * 225 * 128;
    const float* vbg   = Vbias + g * 128 * 225;

    // load q tile [128][32]
    for (int idx = tid; idx < 128 * 32; idx += 256) {
        int c = idx >> 5, x = idx & 31;
        q_s[c * 32 + x] = qbase[c * 1024 + y * 32 + x];
    }
    __syncthreads();

    // ---- QK + rel logits, one window-row (dy) at a time ----
    for (int dy = 0; dy < 15; dy++) {
        const int iy = y + dy - 7;
        const bool rowvalid = (iy >= 0 && iy < 32);

        for (int idx = tid; idx < 128 * 46; idx += 256) {
            int c = idx / 46, px = idx % 46;
            int ix = px - 7;
            float val = 0.f;
            if (rowvalid && ix >= 0 && ix < 32)
                val = kbase[c * 1024 + iy * 32 + ix];
            kv_s[c * 48 + px] = val;
        }
        for (int idx = tid; idx < 15 * 128; idx += 256)
            aux_s[idx] = wrelg[dy * 15 * 128 + idx];
        __syncthreads();

        for (int task = tid; task < 480; task += 256) {
            const int dx = task >> 5, x = task & 31;
            const float* qc = q_s + x;
            const float* kc = kv_s + x + dx;
            const float* wc = aux_s + dx * 128;
            float a1 = 0.f, a2 = 0.f;
            #pragma unroll 8
            for (int c = 0; c < 128; c++) {
                float qv = qc[c * 32];
                a1 += qv * kc[c * 48];
                a2 += qv * wc[c];
            }
            const int wpos = dy * 15 + dx;
            const int ix = x + dx - 7;
            float val = (rowvalid && ix >= 0 && ix < 32)
                            ? (a1 * invT + a2 + brel[g * 225 + wpos])
                            : -1e8f;
            qk_s[wpos * 32 + x] = val;
        }
        __syncthreads();
    }

    // ---- softmax over 225 window positions (8 sub-threads per pixel) ----
    {
        const int x = tid & 31, s = tid >> 5;
        float lm = -1e30f;
        for (int w = s; w < 225; w += 8) lm = fmaxf(lm, qk_s[w * 32 + x]);
        red_s[s * 32 + x] = lm;
        __syncthreads();
        float m = red_s[x];
        #pragma unroll
        for (int i = 1; i < 8; i++) m = fmaxf(m, red_s[i * 32 + x]);
        __syncthreads();   // all reads of red_s done before reuse
        float ls = 0.f;
        for (int w = s; w < 225; w += 8) {
            float e = __expf(qk_s[w * 32 + x] - m);
            qk_s[w * 32 + x] = e;
            ls += e;
        }
        red_s[s * 32 + x] = ls;
        __syncthreads();
        float sum = red_s[x];
        #pragma unroll
        for (int i = 1; i < 8; i++) sum += red_s[i * 32 + x];
        float rinv = 1.f / sum;
        for (int w = s; w < 225; w += 8) qk_s[w * 32 + x] *= rinv;
        __syncthreads();
    }

    // ---- aggregation: out[c][x] = sum_w attn[w][x] * (v_un[c][w][x] + Vbias[c][w]) ----
    const int x  = tid & 31;
    const int cg = tid >> 5;        // 0..7, owns channels cg*16 .. cg*16+15
    const int c0 = cg * 16;
    float acc[16];
    #pragma unroll
    for (int i = 0; i < 16; i++) acc[i] = 0.f;

    for (int dy = 0; dy < 15; dy++) {
        const int iy = y + dy - 7;
        const bool rowvalid = (iy >= 0 && iy < 32);
        __syncthreads();  // previous slab fully consumed
        for (int idx = tid; idx < 128 * 46; idx += 256) {
            int c = idx / 46, px = idx % 46;
            int ix = px - 7;
            float val = 0.f;
            if (rowvalid && ix >= 0 && ix < 32)
                val = vbase[c * 1024 + iy * 32 + ix];
            kv_s[c * 48 + px] = val;
        }
        for (int idx = tid; idx < 128 * 15; idx += 256) {
            int c = idx / 15, dx = idx % 15;
            aux_s[c * 16 + dx] = vbg[c * 225 + dy * 15 + dx];
        }
        __syncthreads();

        for (int dx = 0; dx < 15; dx++) {
            const float aw = qk_s[(dy * 15 + dx) * 32 + x];
            const float* kvp = kv_s + x + dx;
            const float* vbp = aux_s + dx;
            #pragma unroll
            for (int i = 0; i < 16; i++) {
                int c = c0 + i;
                acc[i] += aw * (kvp[c * 48] + vbp[c * 16]);
            }
        }
    }

    // write agg[(m*4 + n)*256 + g*128 + c]
    float* ap = g_agg + ((y * 32 + x) * 4 + n) * 256 + g * 128 + c0;
    #pragma unroll
    for (int i = 0; i < 16; i += 4)
        *(float4*)(ap + i) = make_float4(acc[i], acc[i + 1], acc[i + 2], acc[i + 3]);
}

// ---------------------------------------------------------------------------
// Output FC: out[r, d] = sum_c agg[r, c] * Wfc[d, c] + bfc[d]   (r = m*4+n, 4096 rows)
// ---------------------------------------------------------------------------
__global__ void fc_kernel(const float* __restrict__ Wfc, const float* __restrict__ bfc,
                          float* __restrict__ out) {
    __shared__ float xs[256][36];
    const int r0 = blockIdx.x * 32;
    const int tid = threadIdx.x;

    for (int idx = tid; idx < 32 * 256; idx += 256) {
        int j = idx >> 8, c = idx & 255;
        xs[c][j] = g_agg[(r0 + j) * 256 + c];
    }
    __syncthreads();

    const int d = tid;
    float4 acc[8];
    {
        float bv_ = bfc[d];
        #pragma unroll
        for (int j = 0; j < 8; j++) acc[j] = make_float4(bv_, bv_, bv_, bv_);
    }
    const float* wrow = Wfc + d * 256;
    #pragma unroll 4
    for (int c = 0; c < 256; c++) {
        float wv = wrow[c];
        const float4* xr = (const float4*)xs[c];
        #pragma unroll
        for (int j = 0; j < 8; j++) {
            float4 xv = xr[j];
            acc[j].x += wv * xv.x; acc[j].y += wv * xv.y;
            acc[j].z += wv * xv.z; acc[j].w += wv * xv.w;
        }
    }
    __syncthreads();
    {
        float4* row = (float4*)xs[d];
        #pragma unroll
        for (int j = 0; j < 8; j++) row[j] = acc[j];
    }
    __syncthreads();
    for (int idx = tid; idx < 32 * 256; idx += 256) {
        int j = idx >> 8, c = idx & 255;
        out[(r0 + j) * 256 + c] = xs[c][j];
    }
}

// ---------------------------------------------------------------------------
extern "C" void kernel_launch(void* const* d_in, const int* in_sizes, int n_in,
                              void* d_out, int out_size) {
    const float* q    = (const float*)d_in[0];
    const float* k    = (const float*)d_in[1];
    const float* v    = (const float*)d_in[2];
    const float* Wq   = (const float*)d_in[3];
    const float* bq   = (const float*)d_in[4];
    const float* Wk   = (const float*)d_in[5];
    const float* bk   = (const float*)d_in[6];
    const float* Wv   = (const float*)d_in[7];
    const float* bv   = (const float*)d_in[8];
    const float* Wrel = (const float*)d_in[9];
    const float* brel = (const float*)d_in[10];
    const float* Vb   = (const float*)d_in[11];
    const float* Wfc  = (const float*)d_in[12];
    const float* bfc  = (const float*)d_in[13];
    float* out = (float*)d_out;

    cudaFuncSetAttribute(attn_kernel, cudaFuncAttributeMaxDynamicSharedMemorySize,
                         ATTN_SMEM_BYTES);

    dim3 pg(32, 4, 3);
    proj_kernel<<<pg, 256>>>(q, k, v, Wq, bq, Wk, bk, Wv, bv);

    dim3 ag(32, 2, 4);
    attn_kernel<<<ag, 256, ATTN_SMEM_BYTES>>>(Wrel, brel, Vb);

    fc_kernel<<<128, 256>>>(Wfc, bfc, out);
}

// round 2
// speedup vs baseline: 1.8301x; 1.8301x over previous
#include <cuda_runtime.h>

typedef unsigned long long u64;

// ---------------- f32x2 packed-math helpers (sm_103a) ----------------
__device__ __forceinline__ u64 fma2(u64 a, u64 b, u64 c) {
    u64 d;
    asm("fma.rn.f32x2 %0, %1, %2, %3;" : "=l"(d) : "l"(a), "l"(b), "l"(c));
    return d;
}
__device__ __forceinline__ u64 add2(u64 a, u64 b) {
    u64 d;
    asm("add.rn.f32x2 %0, %1, %2;" : "=l"(d) : "l"(a), "l"(b));
    return d;
}
__device__ __forceinline__ u64 pack2(float lo, float hi) {
    u64 d;
    asm("mov.b64 %0, {%1, %2};" : "=l"(d) : "f"(lo), "f"(hi));
    return d;
}
__device__ __forceinline__ float2 unpack2(u64 v) {
    float2 r;
    asm("mov.b64 {%0, %1}, %2;" : "=f"(r.x), "=f"(r.y) : "l"(v));
    return r;
}

// Problem constants
constexpr int NBATCH = 4;
constexpr int CCH    = 256;
constexpr int HWPIX  = 1024;

// Scratch
__device__ float g_qproj[NBATCH * CCH * HWPIX];
__device__ float g_kproj[NBATCH * CCH * HWPIX];
__device__ float g_vproj[NBATCH * CCH * HWPIX];
__device__ float g_agg[HWPIX * NBATCH * CCH];

// ---------------------------------------------------------------------------
// Projection GEMM: Y[n,d,hw] = sum_c W[d,c] X[n,c,hw] + b[d]
// Block: 64 d x 128 m tile, K=256 in 8 chunks of 32. 256 threads,
// thread micro-tile 4d x 8m (4 f32x2). grid = (32 m-tiles, 4 d-tiles, 3 proj)
// ---------------------------------------------------------------------------
__global__ void __launch_bounds__(256) proj_kernel(
        const float* __restrict__ q, const float* __restrict__ k,
        const float* __restrict__ v,
        const float* __restrict__ Wq, const float* __restrict__ bq,
        const float* __restrict__ Wk, const float* __restrict__ bk,
        const float* __restrict__ Wv, const float* __restrict__ bv) {
    __shared__ float w_s[32 * 68];    // [kk][d] stride 68
    __shared__ float x_s[32 * 128];   // [kk][m] stride 128

    const int p  = blockIdx.z;
    const int m0 = blockIdx.x * 128;
    const int d0 = blockIdx.y * 64;
    const int n  = m0 >> 10;
    const int hw0 = m0 & 1023;
    const int tid = threadIdx.x;

    const float *X, *Wm, *B;
    float* Y;
    if (p == 0)      { X = q; Wm = Wq; B = bq; Y = g_qproj; }
    else if (p == 1) { X = k; Wm = Wk; B = bk; Y = g_kproj; }
    else             { X = v; Wm = Wv; B = bv; Y = g_vproj; }

    const int td = tid >> 4;   // 0..15 -> d rows td*4..+3
    const int tm = tid & 15;   // m cols {2tm+32mq, +1}

    u64 acc[4][4];
    #pragma unroll
    for (int dd = 0; dd < 4; dd++) {
        float b = B[d0 + td * 4 + dd];
        u64 bb = pack2(b, b);
        #pragma unroll
        for (int mq = 0; mq < 4; mq++) acc[dd][mq] = bb;
    }

    // loader indices
    const int ldq = tid >> 3;      // 0..31 (W rows)
    const int lc4 = tid & 7;       // float4 along k
    const int lk  = tid >> 5;      // 0..7 (X rows)
    const int lm4 = tid & 31;      // float4 along m

    for (int kb = 0; kb < 8; kb++) {
        const int k0 = kb * 32;
        // W tile -> w_s[kk][d]
        {
            float4 fa = *(const float4*)(Wm + (d0 + ldq) * 256 + k0 + lc4 * 4);
            float4 fb = *(const float4*)(Wm + (d0 + ldq + 32) * 256 + k0 + lc4 * 4);
            w_s[(lc4 * 4 + 0) * 68 + ldq] = fa.x;
            w_s[(lc4 * 4 + 1) * 68 + ldq] = fa.y;
            w_s[(lc4 * 4 + 2) * 68 + ldq] = fa.z;
            w_s[(lc4 * 4 + 3) * 68 + ldq] = fa.w;
            w_s[(lc4 * 4 + 0) * 68 + ldq + 32] = fb.x;
            w_s[(lc4 * 4 + 1) * 68 + ldq + 32] = fb.y;
            w_s[(lc4 * 4 + 2) * 68 + ldq + 32] = fb.z;
            w_s[(lc4 * 4 + 3) * 68 + ldq + 32] = fb.w;
        }
        // X tile -> x_s[kk][m]
        #pragma unroll
        for (int r = 0; r < 4; r++) {
            *(float4*)(x_s + (lk + 8 * r) * 128 + lm4 * 4) =
                *(const float4*)(X + (n * 256 + k0 + lk + 8 * r) * 1024 + hw0 + lm4 * 4);
        }
        __syncthreads();

        #pragma unroll 8
        for (int kk = 0; kk < 32; kk++) {
            float4 wv = *(const float4*)(w_s + kk * 68 + td * 4);
            u64 xv[4];
            #pragma unroll
            for (int mq = 0; mq < 4; mq++)
                xv[mq] = *(const u64*)(x_s + kk * 128 + 2 * tm + 32 * mq);
            u64 w0 = pack2(wv.x, wv.x), w1 = pack2(wv.y, wv.y);
            u64 w2 = pack2(wv.z, wv.z), w3 = pack2(wv.w, wv.w);
            #pragma unroll
            for (int mq = 0; mq < 4; mq++) {
                acc[0][mq] = fma2(w0, xv[mq], acc[0][mq]);
                acc[1][mq] = fma2(w1, xv[mq], acc[1][mq]);
                acc[2][mq] = fma2(w2, xv[mq], acc[2][mq]);
                acc[3][mq] = fma2(w3, xv[mq], acc[3][mq]);
            }
        }
        __syncthreads();
    }

    #pragma unroll
    for (int dd = 0; dd < 4; dd++) {
        float* yp = Y + (n * 256 + d0 + td * 4 + dd) * 1024 + hw0 + 2 * tm;
        #pragma unroll
        for (int mq = 0; mq < 4; mq++)
            *(float2*)(yp + 32 * mq) = unpack2(acc[dd][mq]);
    }
}

// ---------------------------------------------------------------------------
// Attention kernel: one block per (y, g, n). 256 threads = 8 warps.
// ---------------------------------------------------------------------------
constexpr int OFF_Q   = 0;               // q_s [x][c]  stride 130
constexpr int OFF_KV  = 32 * 130;        // kv  [px][c] stride 130 (46 rows)
constexpr int OFF_AUX = OFF_KV + 46 * 130;   // wrel [dx][c] s128 / vb [dx][c] s132
constexpr int OFF_QK  = OFF_AUX + 1980;      // qk [wpos][x] stride 32
constexpr int OFF_RED = OFF_QK + 225 * 32;
constexpr int ATTN_SMEM_FLOATS = OFF_RED + 256;
constexpr int ATTN_SMEM_BYTES  = ATTN_SMEM_FLOATS * 4;   // 78304

__global__ void __launch_bounds__(256) attn_kernel(
        const float* __restrict__ Wrel, const float* __restrict__ brel,
        const float* __restrict__ Vbias) {
    extern __shared__ float sm[];
    float* q_s  = sm + OFF_Q;
    float* kv_s = sm + OFF_KV;
    float* aux  = sm + OFF_AUX;
    float* qk_s = sm + OFF_QK;
    float* red_s = sm + OFF_RED;

    const int y = blockIdx.x, g = blockIdx.y, n = blockIdx.z;
    const int tid = threadIdx.x;
    const int x = tid & 31, w = tid >> 5;
    const float invT = 0.08838834764831845f;

    const float* qb  = g_qproj + (n * 2 + g) * 131072;
    const float* kb  = g_kproj + (n * 2 + g) * 131072;
    const float* vbp = g_vproj + (n * 2 + g) * 131072;
    const float* wrelg = Wrel + g * 28800;
    const float* vbg   = Vbias + g * 28800;

    // q tile, transposed to [x][c]
    for (int i = tid; i < 4096; i += 256) {
        int c = i >> 5, xx = i & 31;
        q_s[xx * 130 + c] = qb[c * 1024 + y * 32 + xx];
    }
    // zero permanent out-of-image edge columns of kv slab (px 0..6, 39..45)
    for (int i = tid; i < 14 * 128; i += 256) {
        int e = i >> 7, c = i & 127;
        int px = (e < 7) ? e : e + 32;
        kv_s[px * 130 + c] = 0.f;
    }
    __syncthreads();

    // ---------------- QK + rel logits ----------------
    const int dx0 = w;
    const int dx1 = (w < 7) ? w + 8 : 0;
    for (int dy = 0; dy < 15; dy++) {
        const int iy = y + dy - 7;
        const bool rv = (iy >= 0) && (iy < 32);
        for (int i = tid; i < 4096; i += 256) {
            int c = i >> 5, ix = i & 31;
            kv_s[(ix + 7) * 130 + c] = rv ? kb[c * 1024 + iy * 32 + ix] * invT : 0.f;
        }
        for (int i = tid; i < 1920; i += 256)
            aux[i] = wrelg[dy * 1920 + i];
        __syncthreads();

        u64 a0k = 0, a0w = 0, a1k = 0, a1w = 0;
        const float* qp  = q_s + x * 130;
        const float* kp0 = kv_s + (x + dx0) * 130;
        const float* kp1 = kv_s + (x + dx1) * 130;
        const float* wp0 = aux + dx0 * 128;
        const float* wp1 = aux + dx1 * 128;
        #pragma unroll 16
        for (int c2 = 0; c2 < 64; c2++) {
            u64 q2 = *(const u64*)(qp + 2 * c2);
            a0k = fma2(q2, *(const u64*)(kp0 + 2 * c2), a0k);
            a0w = fma2(q2, *(const u64*)(wp0 + 2 * c2), a0w);
            a1k = fma2(q2, *(const u64*)(kp1 + 2 * c2), a1k);
            a1w = fma2(q2, *(const u64*)(wp1 + 2 * c2), a1w);
        }
        {
            float2 t0 = unpack2(a0k), t1 = unpack2(a0w);
            float l0 = t0.x + t0.y + t1.x + t1.y;
            int px = x + dx0;
            bool val = rv && (px >= 7) && (px < 39);
            qk_s[(dy * 15 + dx0) * 32 + x] =
                val ? l0 + brel[g * 225 + dy * 15 + dx0] : -1e8f;
        }
        if (w < 7) {
            float2 t0 = unpack2(a1k), t1 = unpack2(a1w);
            float l1 = t0.x + t0.y + t1.x + t1.y;
            int px = x + dx1;
            bool val = rv && (px >= 7) && (px < 39);
            qk_s[(dy * 15 + dx1) * 32 + x] =
                val ? l1 + brel[g * 225 + dy * 15 + dx1] : -1e8f;
        }
        __syncthreads();
    }

    // ---------------- softmax over 225 positions ----------------
    {
        float lm = -1e30f;
        for (int ww = w; ww < 225; ww += 8) lm = fmaxf(lm, qk_s[ww * 32 + x]);
        red_s[w * 32 + x] = lm;
        __syncthreads();
        float m = red_s[x];
        #pragma unroll
        for (int i = 1; i < 8; i++) m = fmaxf(m, red_s[i * 32 + x]);
        __syncthreads();
        float ls = 0.f;
        for (int ww = w; ww < 225; ww += 8) {
            float e = __expf(qk_s[ww * 32 + x] - m);
            qk_s[ww * 32 + x] = e;
            ls += e;
        }
        red_s[w * 32 + x] = ls;
        __syncthreads();
        float s = red_s[x];
        #pragma unroll
        for (int i = 1; i < 8; i++) s += red_s[i * 32 + x];
        float rinv = 1.f / s;
        for (int ww = w; ww < 225; ww += 8) qk_s[ww * 32 + x] *= rinv;
    }

    // ---------------- aggregation ----------------
    u64 acc[8];
    #pragma unroll
    for (int j = 0; j < 8; j++) acc[j] = 0;
    const int cbase = w * 16;

    for (int dy = 0; dy < 15; dy++) {
        const int iy = y + dy - 7;
        const bool rv = (iy >= 0) && (iy < 32);
        __syncthreads();
        for (int i = tid; i < 4096; i += 256) {
            int c = i >> 5, ix = i & 31;
            kv_s[(ix + 7) * 130 + c] = rv ? vbp[c * 1024 + iy * 32 + ix] : 0.f;
        }
        for (int i = tid; i < 1920; i += 256) {
            int c = i / 15, dxx = i % 15;
            aux[dxx * 132 + c] = __ldg(vbg + c * 225 + dy * 15 + dxx);
        }
        __syncthreads();

        #pragma unroll 5
        for (int dx = 0; dx < 15; dx++) {
            float aw = qk_s[(dy * 15 + dx) * 32 + x];
            u64 aw2 = pack2(aw, aw);
            const float* vp = kv_s + (x + dx) * 130 + cbase;
            const float* bp = aux + dx * 132 + cbase;
            #pragma unroll
            for (int j = 0; j < 8; j++)
                acc[j] = fma2(aw2,
                              add2(*(const u64*)(vp + 2 * j), *(const u64*)(bp + 2 * j)),
                              acc[j]);
        }
    }

    float* ap = g_agg + ((y * 32 + x) * 4 + n) * 256 + g * 128 + cbase;
    #pragma unroll
    for (int j = 0; j < 8; j++) *(float2*)(ap + 2 * j) = unpack2(acc[j]);
}

// ---------------------------------------------------------------------------
// Output FC: out[r, d] = sum_c agg[r, c] * Wfc[d, c] + bfc[d]
// Block: 64 r x 128 d tile. grid = (64 r-tiles, 2 d-tiles)
// ---------------------------------------------------------------------------
__global__ void __launch_bounds__(256) fc_kernel(
        const float* __restrict__ Wfc, const float* __restrict__ bfc,
        float* __restrict__ out) {
    __shared__ float w_s[32 * 68];    // [kk][r]
    __shared__ float x_s[32 * 128];   // [kk][d]

    const int r0 = blockIdx.x * 64;
    const int d0 = blockIdx.y * 128;
    const int tid = threadIdx.x;
    const int td = tid >> 4;   // r rows td*4..+3
    const int tm = tid & 15;   // d cols {2tm+32mq, +1}

    u64 acc[4][4];
    #pragma unroll
    for (int mq = 0; mq < 4; mq++) {
        int d = d0 + 2 * tm + 32 * mq;
        u64 bb = pack2(bfc[d], bfc[d + 1]);
        #pragma unroll
        for (int rr = 0; rr < 4; rr++) acc[rr][mq] = bb;
    }

    const int lrq = tid >> 3;   // 0..31 (agg rows)
    const int lc4 = tid & 7;
    const int ld  = tid & 127;  // Wfc row d
    const int lch = tid >> 7;   // 0..1

    for (int kb = 0; kb < 8; kb++) {
        const int k0 = kb * 32;
        {
            float4 fa = *(const float4*)(g_agg + (r0 + lrq) * 256 + k0 + lc4 * 4);
            float4 fb = *(const float4*)(g_agg + (r0 + lrq + 32) * 256 + k0 + lc4 * 4);
            w_s[(lc4 * 4 + 0) * 68 + lrq] = fa.x;
            w_s[(lc4 * 4 + 1) * 68 + lrq] = fa.y;
            w_s[(lc4 * 4 + 2) * 68 + lrq] = fa.z;
            w_s[(lc4 * 4 + 3) * 68 + lrq] = fa.w;
            w_s[(lc4 * 4 + 0) * 68 + lrq + 32] = fb.x;
            w_s[(lc4 * 4 + 1) * 68 + lrq + 32] = fb.y;
            w_s[(lc4 * 4 + 2) * 68 + lrq + 32] = fb.z;
            w_s[(lc4 * 4 + 3) * 68 + lrq + 32] = fb.w;
        }
        #pragma unroll
        for (int i = 0; i < 4; i++) {
            int cq = lch * 4 + i;
            float4 f = *(const float4*)(Wfc + (d0 + ld) * 256 + k0 + cq * 4);
            x_s[(cq * 4 + 0) * 128 + ld] = f.x;
            x_s[(cq * 4 + 1) * 128 + ld] = f.y;
            x_s[(cq * 4 + 2) * 128 + ld] = f.z;
            x_s[(cq * 4 + 3) * 128 + ld] = f.w;
        }
        __syncthreads();

        #pragma unroll 8
        for (int kk = 0; kk < 32; kk++) {
            float4 wv = *(const float4*)(w_s + kk * 68 + td * 4);
            u64 xv[4];
            #pragma unroll
            for (int mq = 0; mq < 4; mq++)
                xv[mq] = *(const u64*)(x_s + kk * 128 + 2 * tm + 32 * mq);
            u64 w0 = pack2(wv.x, wv.x), w1 = pack2(wv.y, wv.y);
            u64 w2 = pack2(wv.z, wv.z), w3 = pack2(wv.w, wv.w);
            #pragma unroll
            for (int mq = 0; mq < 4; mq++) {
                acc[0][mq] = fma2(w0, xv[mq], acc[0][mq]);
                acc[1][mq] = fma2(w1, xv[mq], acc[1][mq]);
                acc[2][mq] = fma2(w2, xv[mq], acc[2][mq]);
                acc[3][mq] = fma2(w3, xv[mq], acc[3][mq]);
            }
        }
        __syncthreads();
    }

    #pragma unroll
    for (int rr = 0; rr < 4; rr++) {
        float* op = out + (r0 + td * 4 + rr) * 256 + d0 + 2 * tm;
        #pragma unroll
        for (int mq = 0; mq < 4; mq++)
            *(float2*)(op + 32 * mq) = unpack2(acc[rr][mq]);
    }
}

// ---------------------------------------------------------------------------
extern "C" void kernel_launch(void* const* d_in, const int* in_sizes, int n_in,
                              void* d_out, int out_size) {
    const float* q    = (const float*)d_in[0];
    const float* k    = (const float*)d_in[1];
    const float* v    = (const float*)d_in[2];
    const float* Wq   = (const float*)d_in[3];
    const float* bq   = (const float*)d_in[4];
    const float* Wk   = (const float*)d_in[5];
    const float* bk   = (const float*)d_in[6];
    const float* Wv   = (const float*)d_in[7];
    const float* bv   = (const float*)d_in[8];
    const float* Wrel = (const float*)d_in[9];
    const float* brel = (const float*)d_in[10];
    const float* Vb   = (const float*)d_in[11];
    const float* Wfc  = (const float*)d_in[12];
    const float* bfc  = (const float*)d_in[13];
    float* out = (float*)d_out;

    cudaFuncSetAttribute(attn_kernel, cudaFuncAttributeMaxDynamicSharedMemorySize,
                         ATTN_SMEM_BYTES);

    dim3 pg(32, 4, 3);
    proj_kernel<<<pg, 256>>>(q, k, v, Wq, bq, Wk, bk, Wv, bv);

    dim3 ag(32, 2, 4);
    attn_kernel<<<ag, 256, ATTN_SMEM_BYTES>>>(Wrel, brel, Vb);

    dim3 fg(64, 2);
    fc_kernel<<<fg, 256>>>(Wfc, bfc, out);
}

// round 3
// speedup vs baseline: 1.9061x; 1.0415x over previous
#include <cuda_runtime.h>

typedef unsigned long long u64;

// ---------------- f32x2 packed-math helpers (sm_103a) ----------------
__device__ __forceinline__ u64 fma2(u64 a, u64 b, u64 c) {
    u64 d;
    asm("fma.rn.f32x2 %0, %1, %2, %3;" : "=l"(d) : "l"(a), "l"(b), "l"(c));
    return d;
}
__device__ __forceinline__ u64 add2(u64 a, u64 b) {
    u64 d;
    asm("add.rn.f32x2 %0, %1, %2;" : "=l"(d) : "l"(a), "l"(b));
    return d;
}
__device__ __forceinline__ u64 pack2(float lo, float hi) {
    u64 d;
    asm("mov.b64 %0, {%1, %2};" : "=l"(d) : "f"(lo), "f"(hi));
    return d;
}
__device__ __forceinline__ float2 unpack2(u64 v) {
    float2 r;
    asm("mov.b64 {%0, %1}, %2;" : "=f"(r.x), "=f"(r.y) : "l"(v));
    return r;
}

// Problem constants
constexpr int NBATCH = 4;
constexpr int CCH    = 256;
constexpr int HWPIX  = 1024;

// Scratch
__device__ float g_qproj[NBATCH * CCH * HWPIX];
__device__ float g_kproj[NBATCH * CCH * HWPIX];
__device__ float g_vproj[NBATCH * CCH * HWPIX];
__device__ float g_agg[HWPIX * NBATCH * CCH];

// ---------------------------------------------------------------------------
// Projection GEMM: Y[n,d,hw] = sum_c W[d,c] X[n,c,hw] + b[d]
// Block: 64 d x 128 m tile, K=256 in 8 chunks of 32. 256 threads,
// thread micro-tile 4d x 8m (4 f32x2). grid = (32 m-tiles, 4 d-tiles, 3 proj)
// ---------------------------------------------------------------------------
__global__ void __launch_bounds__(256) proj_kernel(
        const float* __restrict__ q, const float* __restrict__ k,
        const float* __restrict__ v,
        const float* __restrict__ Wq, const float* __restrict__ bq,
        const float* __restrict__ Wk, const float* __restrict__ bk,
        const float* __restrict__ Wv, const float* __restrict__ bv) {
    __shared__ float w_s[32 * 68];    // [kk][d] stride 68
    __shared__ float x_s[32 * 128];   // [kk][m] stride 128

    const int p  = blockIdx.z;
    const int m0 = blockIdx.x * 128;
    const int d0 = blockIdx.y * 64;
    const int n  = m0 >> 10;
    const int hw0 = m0 & 1023;
    const int tid = threadIdx.x;

    const float *X, *Wm, *B;
    float* Y;
    if (p == 0)      { X = q; Wm = Wq; B = bq; Y = g_qproj; }
    else if (p == 1) { X = k; Wm = Wk; B = bk; Y = g_kproj; }
    else             { X = v; Wm = Wv; B = bv; Y = g_vproj; }

    const int td = tid >> 4;   // 0..15 -> d rows td*4..+3
    const int tm = tid & 15;   // m cols {2tm+32mq, +1}

    u64 acc[4][4];
    #pragma unroll
    for (int dd = 0; dd < 4; dd++) {
        float b = B[d0 + td * 4 + dd];
        u64 bb = pack2(b, b);
        #pragma unroll
        for (int mq = 0; mq < 4; mq++) acc[dd][mq] = bb;
    }

    // loader indices
    const int ldq = tid >> 3;      // 0..31 (W rows)
    const int lc4 = tid & 7;       // float4 along k
    const int lk  = tid >> 5;      // 0..7 (X rows)
    const int lm4 = tid & 31;      // float4 along m

    for (int kb = 0; kb < 8; kb++) {
        const int k0 = kb * 32;
        // W tile -> w_s[kk][d]
        {
            float4 fa = *(const float4*)(Wm + (d0 + ldq) * 256 + k0 + lc4 * 4);
            float4 fb = *(const float4*)(Wm + (d0 + ldq + 32) * 256 + k0 + lc4 * 4);
            w_s[(lc4 * 4 + 0) * 68 + ldq] = fa.x;
            w_s[(lc4 * 4 + 1) * 68 + ldq] = fa.y;
            w_s[(lc4 * 4 + 2) * 68 + ldq] = fa.z;
            w_s[(lc4 * 4 + 3) * 68 + ldq] = fa.w;
            w_s[(lc4 * 4 + 0) * 68 + ldq + 32] = fb.x;
            w_s[(lc4 * 4 + 1) * 68 + ldq + 32] = fb.y;
            w_s[(lc4 * 4 + 2) * 68 + ldq + 32] = fb.z;
            w_s[(lc4 * 4 + 3) * 68 + ldq + 32] = fb.w;
        }
        // X tile -> x_s[kk][m]
        #pragma unroll
        for (int r = 0; r < 4; r++) {
            *(float4*)(x_s + (lk + 8 * r) * 128 + lm4 * 4) =
                *(const float4*)(X + (n * 256 + k0 + lk + 8 * r) * 1024 + hw0 + lm4 * 4);
        }
        __syncthreads();

        #pragma unroll 8
        for (int kk = 0; kk < 32; kk++) {
            float4 wv = *(const float4*)(w_s + kk * 68 + td * 4);
            u64 xv[4];
            #pragma unroll
            for (int mq = 0; mq < 4; mq++)
                xv[mq] = *(const u64*)(x_s + kk * 128 + 2 * tm + 32 * mq);
            u64 w0 = pack2(wv.x, wv.x), w1 = pack2(wv.y, wv.y);
            u64 w2 = pack2(wv.z, wv.z), w3 = pack2(wv.w, wv.w);
            #pragma unroll
            for (int mq = 0; mq < 4; mq++) {
                acc[0][mq] = fma2(w0, xv[mq], acc[0][mq]);
                acc[1][mq] = fma2(w1, xv[mq], acc[1][mq]);
                acc[2][mq] = fma2(w2, xv[mq], acc[2][mq]);
                acc[3][mq] = fma2(w3, xv[mq], acc[3][mq]);
            }
        }
        __syncthreads();
    }

    #pragma unroll
    for (int dd = 0; dd < 4; dd++) {
        float* yp = Y + (n * 256 + d0 + td * 4 + dd) * 1024 + hw0 + 2 * tm;
        #pragma unroll
        for (int mq = 0; mq < 4; mq++)
            *(float2*)(yp + 32 * mq) = unpack2(acc[dd][mq]);
    }
}

// ---------------------------------------------------------------------------
// Attention kernel: one block per (y, g, n). 256 threads = 8 warps.
// ---------------------------------------------------------------------------
constexpr int OFF_Q   = 0;               // q_s [x][c]  stride 130
constexpr int OFF_KV  = 32 * 130;        // kv  [px][c] stride 130 (46 rows)
constexpr int OFF_AUX = OFF_KV + 46 * 130;   // wrel [dx][c] s128 / vb [dx][c] s132
constexpr int OFF_QK  = OFF_AUX + 1980;      // qk [wpos][x] stride 32
constexpr int OFF_RED = OFF_QK + 225 * 32;
constexpr int ATTN_SMEM_FLOATS = OFF_RED + 256;
constexpr int ATTN_SMEM_BYTES  = ATTN_SMEM_FLOATS * 4;   // 78304

__global__ void __launch_bounds__(256) attn_kernel(
        const float* __restrict__ Wrel, const float* __restrict__ brel,
        const float* __restrict__ Vbias) {
    extern __shared__ float sm[];
    float* q_s  = sm + OFF_Q;
    float* kv_s = sm + OFF_KV;
    float* aux  = sm + OFF_AUX;
    float* qk_s = sm + OFF_QK;
    float* red_s = sm + OFF_RED;

    const int y = blockIdx.x, g = blockIdx.y, n = blockIdx.z;
    const int tid = threadIdx.x;
    const int x = tid & 31, w = tid >> 5;
    const float invT = 0.08838834764831845f;

    const float* qb  = g_qproj + (n * 2 + g) * 131072;
    const float* kb  = g_kproj + (n * 2 + g) * 131072;
    const float* vbp = g_vproj + (n * 2 + g) * 131072;
    const float* wrelg = Wrel + g * 28800;
    const float* vbg   = Vbias + g * 28800;

    // q tile, transposed to [x][c]
    for (int i = tid; i < 4096; i += 256) {
        int c = i >> 5, xx = i & 31;
        q_s[xx * 130 + c] = qb[c * 1024 + y * 32 + xx];
    }
    // zero permanent out-of-image edge columns of kv slab (px 0..6, 39..45)
    for (int i = tid; i < 14 * 128; i += 256) {
        int e = i >> 7, c = i & 127;
        int px = (e < 7) ? e : e + 32;
        kv_s[px * 130 + c] = 0.f;
    }
    __syncthreads();

    // ---------------- QK + rel logits ----------------
    const int dx0 = w;
    const int dx1 = (w < 7) ? w + 8 : 0;
    for (int dy = 0; dy < 15; dy++) {
        const int iy = y + dy - 7;
        const bool rv = (iy >= 0) && (iy < 32);
        for (int i = tid; i < 4096; i += 256) {
            int c = i >> 5, ix = i & 31;
            kv_s[(ix + 7) * 130 + c] = rv ? kb[c * 1024 + iy * 32 + ix] * invT : 0.f;
        }
        for (int i = tid; i < 1920; i += 256)
            aux[i] = wrelg[dy * 1920 + i];
        __syncthreads();

        u64 a0k = 0, a0w = 0, a1k = 0, a1w = 0;
        const float* qp  = q_s + x * 130;
        const float* kp0 = kv_s + (x + dx0) * 130;
        const float* kp1 = kv_s + (x + dx1) * 130;
        const float* wp0 = aux + dx0 * 128;
        const float* wp1 = aux + dx1 * 128;
        #pragma unroll 16
        for (int c2 = 0; c2 < 64; c2++) {
            u64 q2 = *(const u64*)(qp + 2 * c2);
            a0k = fma2(q2, *(const u64*)(kp0 + 2 * c2), a0k);
            a0w = fma2(q2, *(const u64*)(wp0 + 2 * c2), a0w);
            a1k = fma2(q2, *(const u64*)(kp1 + 2 * c2), a1k);
            a1w = fma2(q2, *(const u64*)(wp1 + 2 * c2), a1w);
        }
        {
            float2 t0 = unpack2(a0k), t1 = unpack2(a0w);
            float l0 = t0.x + t0.y + t1.x + t1.y;
            int px = x + dx0;
            bool val = rv && (px >= 7) && (px < 39);
            qk_s[(dy * 15 + dx0) * 32 + x] =
                val ? l0 + brel[g * 225 + dy * 15 + dx0] : -1e8f;
        }
        if (w < 7) {
            float2 t0 = unpack2(a1k), t1 = unpack2(a1w);
            float l1 = t0.x + t0.y + t1.x + t1.y;
            int px = x + dx1;
            bool val = rv && (px >= 7) && (px < 39);
            qk_s[(dy * 15 + dx1) * 32 + x] =
                val ? l1 + brel[g * 225 + dy * 15 + dx1] : -1e8f;
        }
        __syncthreads();
    }

    // ---------------- softmax over 225 positions ----------------
    {
        float lm = -1e30f;
        for (int ww = w; ww < 225; ww += 8) lm = fmaxf(lm, qk_s[ww * 32 + x]);
        red_s[w * 32 + x] = lm;
        __syncthreads();
        float m = red_s[x];
        #pragma unroll
        for (int i = 1; i < 8; i++) m = fmaxf(m, red_s[i * 32 + x]);
        __syncthreads();
        float ls = 0.f;
        for (int ww = w; ww < 225; ww += 8) {
            float e = __expf(qk_s[ww * 32 + x] - m);
            qk_s[ww * 32 + x] = e;
            ls += e;
        }
        red_s[w * 32 + x] = ls;
        __syncthreads();
        float s = red_s[x];
        #pragma unroll
        for (int i = 1; i < 8; i++) s += red_s[i * 32 + x];
        float rinv = 1.f / s;
        for (int ww = w; ww < 225; ww += 8) qk_s[ww * 32 + x] *= rinv;
    }

    // ---------------- aggregation ----------------
    u64 acc[8];
    #pragma unroll
    for (int j = 0; j < 8; j++) acc[j] = 0;
    const int cbase = w * 16;

    for (int dy = 0; dy < 15; dy++) {
        const int iy = y + dy - 7;
        const bool rv = (iy >= 0) && (iy < 32);
        __syncthreads();
        for (int i = tid; i < 4096; i += 256) {
            int c = i >> 5, ix = i & 31;
            kv_s[(ix + 7) * 130 + c] = rv ? vbp[c * 1024 + iy * 32 + ix] : 0.f;
        }
        for (int i = tid; i < 1920; i += 256) {
            int c = i / 15, dxx = i % 15;
            aux[dxx * 132 + c] = __ldg(vbg + c * 225 + dy * 15 + dxx);
        }
        __syncthreads();

        #pragma unroll 5
        for (int dx = 0; dx < 15; dx++) {
            float aw = qk_s[(dy * 15 + dx) * 32 + x];
            u64 aw2 = pack2(aw, aw);
            const float* vp = kv_s + (x + dx) * 130 + cbase;
            const float* bp = aux + dx * 132 + cbase;
            #pragma unroll
            for (int j = 0; j < 8; j++)
                acc[j] = fma2(aw2,
                              add2(*(const u64*)(vp + 2 * j), *(const u64*)(bp + 2 * j)),
                              acc[j]);
        }
    }

    float* ap = g_agg + ((y * 32 + x) * 4 + n) * 256 + g * 128 + cbase;
    #pragma unroll
    for (int j = 0; j < 8; j++) *(float2*)(ap + 2 * j) = unpack2(acc[j]);
}

// ---------------------------------------------------------------------------
// Output FC: out[r, d] = sum_c agg[r, c] * Wfc[d, c] + bfc[d]
// Block: 64 r x 128 d tile. grid = (64 r-tiles, 2 d-tiles)
// ---------------------------------------------------------------------------
__global__ void __launch_bounds__(256) fc_kernel(
        const float* __restrict__ Wfc, const float* __restrict__ bfc,
        float* __restrict__ out) {
    __shared__ float w_s[32 * 68];    // [kk][r]
    __shared__ float x_s[32 * 128];   // [kk][d]

    const int r0 = blockIdx.x * 64;
    const int d0 = blockIdx.y * 128;
    const int tid = threadIdx.x;
    const int td = tid >> 4;   // r rows td*4..+3
    const int tm = tid & 15;   // d cols {2tm+32mq, +1}

    u64 acc[4][4];
    #pragma unroll
    for (int mq = 0; mq < 4; mq++) {
        int d = d0 + 2 * tm + 32 * mq;
        u64 bb = pack2(bfc[d], bfc[d + 1]);
        #pragma unroll
        for (int rr = 0; rr < 4; rr++) acc[rr][mq] = bb;
    }

    const int lrq = tid >> 3;   // 0..31 (agg rows)
    const int lc4 = tid & 7;
    const int ld  = tid & 127;  // Wfc row d
    const int lch = tid >> 7;   // 0..1

    for (int kb = 0; kb < 8; kb++) {
        const int k0 = kb * 32;
        {
            float4 fa = *(const float4*)(g_agg + (r0 + lrq) * 256 + k0 + lc4 * 4);
            float4 fb = *(const float4*)(g_agg + (r0 + lrq + 32) * 256 + k0 + lc4 * 4);
            w_s[(lc4 * 4 + 0) * 68 + lrq] = fa.x;
            w_s[(lc4 * 4 + 1) * 68 + lrq] = fa.y;
            w_s[(lc4 * 4 + 2) * 68 + lrq] = fa.z;
            w_s[(lc4 * 4 + 3) * 68 + lrq] = fa.w;
            w_s[(lc4 * 4 + 0) * 68 + lrq + 32] = fb.x;
            w_s[(lc4 * 4 + 1) * 68 + lrq + 32] = fb.y;
            w_s[(lc4 * 4 + 2) * 68 + lrq + 32] = fb.z;
            w_s[(lc4 * 4 + 3) * 68 + lrq + 32] = fb.w;
        }
        #pragma unroll
        for (int i = 0; i < 4; i++) {
            int cq = lch * 4 + i;
            float4 f = *(const float4*)(Wfc + (d0 + ld) * 256 + k0 + cq * 4);
            x_s[(cq * 4 + 0) * 128 + ld] = f.x;
            x_s[(cq * 4 + 1) * 128 + ld] = f.y;
            x_s[(cq * 4 + 2) * 128 + ld] = f.z;
            x_s[(cq * 4 + 3) * 128 + ld] = f.w;
        }
        __syncthreads();

        #pragma unroll 8
        for (int kk = 0; kk < 32; kk++) {
            float4 wv = *(const float4*)(w_s + kk * 68 + td * 4);
            u64 xv[4];
            #pragma unroll
            for (int mq = 0; mq < 4; mq++)
                xv[mq] = *(const u64*)(x_s + kk * 128 + 2 * tm + 32 * mq);
            u64 w0 = pack2(wv.x, wv.x), w1 = pack2(wv.y, wv.y);
            u64 w2 = pack2(wv.z, wv.z), w3 = pack2(wv.w, wv.w);
            #pragma unroll
            for (int mq = 0; mq < 4; mq++) {
                acc[0][mq] = fma2(w0, xv[mq], acc[0][mq]);
                acc[1][mq] = fma2(w1, xv[mq], acc[1][mq]);
                acc[2][mq] = fma2(w2, xv[mq], acc[2][mq]);
                acc[3][mq] = fma2(w3, xv[mq], acc[3][mq]);
            }
        }
        __syncthreads();
    }

    #pragma unroll
    for (int rr = 0; rr < 4; rr++) {
        float* op = out + (r0 + td * 4 + rr) * 256 + d0 + 2 * tm;
        #pragma unroll
        for (int mq = 0; mq < 4; mq++)
            *(float2*)(op + 32 * mq) = unpack2(acc[rr][mq]);
    }
}

// ---------------------------------------------------------------------------
extern "C" void kernel_launch(void* const* d_in, const int* in_sizes, int n_in,
                              void* d_out, int out_size) {
    const float* q    = (const float*)d_in[0];
    const float* k    = (const float*)d_in[1];
    const float* v    = (const float*)d_in[2];
    const float* Wq   = (const float*)d_in[3];
    const float* bq   = (const float*)d_in[4];
    const float* Wk   = (const float*)d_in[5];
    const float* bk   = (const float*)d_in[6];
    const float* Wv   = (const float*)d_in[7];
    const float* bv   = (const float*)d_in[8];
    const float* Wrel = (const float*)d_in[9];
    const float* brel = (const float*)d_in[10];
    const float* Vb   = (const float*)d_in[11];
    const float* Wfc  = (const float*)d_in[12];
    const float* bfc  = (const float*)d_in[13];
    float* out = (float*)d_out;

    cudaFuncSetAttribute(attn_kernel, cudaFuncAttributeMaxDynamicSharedMemorySize,
                         ATTN_SMEM_BYTES);

    dim3 pg(32, 4, 3);
    proj_kernel<<<pg, 256>>>(q, k, v, Wq, bq, Wk, bk, Wv, bv);

    dim3 ag(32, 2, 4);
    attn_kernel<<<ag, 256, ATTN_SMEM_BYTES>>>(Wrel, brel, Vb);

    dim3 fg(64, 2);
    fc_kernel<<<fg, 256>>>(Wfc, bfc, out);
}

// round 4
// speedup vs baseline: 1.9769x; 1.0371x over previous
#include <cuda_runtime.h>

typedef unsigned long long u64;

// ---------------- f32x2 packed-math helpers (sm_103a) ----------------
__device__ __forceinline__ u64 fma2(u64 a, u64 b, u64 c) {
    u64 d;
    asm("fma.rn.f32x2 %0, %1, %2, %3;" : "=l"(d) : "l"(a), "l"(b), "l"(c));
    return d;
}
__device__ __forceinline__ u64 add2(u64 a, u64 b) {
    u64 d;
    asm("add.rn.f32x2 %0, %1, %2;" : "=l"(d) : "l"(a), "l"(b));
    return d;
}
__device__ __forceinline__ u64 pack2(float lo, float hi) {
    u64 d;
    asm("mov.b64 %0, {%1, %2};" : "=l"(d) : "f"(lo), "f"(hi));
    return d;
}
__device__ __forceinline__ float2 unpack2(u64 v) {
    float2 r;
    asm("mov.b64 {%0, %1}, %2;" : "=f"(r.x), "=f"(r.y) : "l"(v));
    return r;
}

// Problem constants
constexpr int NBATCH = 4;
constexpr int CCH    = 256;
constexpr int HWPIX  = 1024;

// Scratch
__device__ float g_qproj[NBATCH * CCH * HWPIX];
__device__ float g_kproj[NBATCH * CCH * HWPIX];
__device__ float g_vproj[NBATCH * CCH * HWPIX];
__device__ float g_agg[HWPIX * NBATCH * CCH];
__device__ float g_logits[8 * 225 * 1024];   // [ng][wpos][pix]

// ---------------------------------------------------------------------------
// Projection GEMM: Y[n,d,hw] = sum_c W[d,c] X[n,c,hw] + b[d]
// ---------------------------------------------------------------------------
__global__ void __launch_bounds__(256) proj_kernel(
        const float* __restrict__ q, const float* __restrict__ k,
        const float* __restrict__ v,
        const float* __restrict__ Wq, const float* __restrict__ bq,
        const float* __restrict__ Wk, const float* __restrict__ bk,
        const float* __restrict__ Wv, const float* __restrict__ bv) {
    __shared__ float w_s[32 * 68];    // [kk][d] stride 68
    __shared__ float x_s[32 * 128];   // [kk][m] stride 128

    const int p  = blockIdx.z;
    const int m0 = blockIdx.x * 128;
    const int d0 = blockIdx.y * 64;
    const int n  = m0 >> 10;
    const int hw0 = m0 & 1023;
    const int tid = threadIdx.x;

    const float *X, *Wm, *B;
    float* Y;
    if (p == 0)      { X = q; Wm = Wq; B = bq; Y = g_qproj; }
    else if (p == 1) { X = k; Wm = Wk; B = bk; Y = g_kproj; }
    else             { X = v; Wm = Wv; B = bv; Y = g_vproj; }

    const int td = tid >> 4;
    const int tm = tid & 15;

    u64 acc[4][4];
    #pragma unroll
    for (int dd = 0; dd < 4; dd++) {
        float b = B[d0 + td * 4 + dd];
        u64 bb = pack2(b, b);
        #pragma unroll
        for (int mq = 0; mq < 4; mq++) acc[dd][mq] = bb;
    }

    const int ldq = tid >> 3;
    const int lc4 = tid & 7;
    const int lk  = tid >> 5;
    const int lm4 = tid & 31;

    for (int kb = 0; kb < 8; kb++) {
        const int k0 = kb * 32;
        {
            float4 fa = *(const float4*)(Wm + (d0 + ldq) * 256 + k0 + lc4 * 4);
            float4 fb = *(const float4*)(Wm + (d0 + ldq + 32) * 256 + k0 + lc4 * 4);
            w_s[(lc4 * 4 + 0) * 68 + ldq] = fa.x;
            w_s[(lc4 * 4 + 1) * 68 + ldq] = fa.y;
            w_s[(lc4 * 4 + 2) * 68 + ldq] = fa.z;
            w_s[(lc4 * 4 + 3) * 68 + ldq] = fa.w;
            w_s[(lc4 * 4 + 0) * 68 + ldq + 32] = fb.x;
            w_s[(lc4 * 4 + 1) * 68 + ldq + 32] = fb.y;
            w_s[(lc4 * 4 + 2) * 68 + ldq + 32] = fb.z;
            w_s[(lc4 * 4 + 3) * 68 + ldq + 32] = fb.w;
        }
        #pragma unroll
        for (int r = 0; r < 4; r++) {
            *(float4*)(x_s + (lk + 8 * r) * 128 + lm4 * 4) =
                *(const float4*)(X + (n * 256 + k0 + lk + 8 * r) * 1024 + hw0 + lm4 * 4);
        }
        __syncthreads();

        #pragma unroll 8
        for (int kk = 0; kk < 32; kk++) {
            float4 wv = *(const float4*)(w_s + kk * 68 + td * 4);
            u64 xv[4];
            #pragma unroll
            for (int mq = 0; mq < 4; mq++)
                xv[mq] = *(const u64*)(x_s + kk * 128 + 2 * tm + 32 * mq);
            u64 w0 = pack2(wv.x, wv.x), w1 = pack2(wv.y, wv.y);
            u64 w2 = pack2(wv.z, wv.z), w3 = pack2(wv.w, wv.w);
            #pragma unroll
            for (int mq = 0; mq < 4; mq++) {
                acc[0][mq] = fma2(w0, xv[mq], acc[0][mq]);
                acc[1][mq] = fma2(w1, xv[mq], acc[1][mq]);
                acc[2][mq] = fma2(w2, xv[mq], acc[2][mq]);
                acc[3][mq] = fma2(w3, xv[mq], acc[3][mq]);
            }
        }
        __syncthreads();
    }

    #pragma unroll
    for (int dd = 0; dd < 4; dd++) {
        float* yp = Y + (n * 256 + d0 + td * 4 + dd) * 1024 + hw0 + 2 * tm;
        #pragma unroll
        for (int mq = 0; mq < 4; mq++)
            *(float2*)(yp + 32 * mq) = unpack2(acc[dd][mq]);
    }
}

// ---------------------------------------------------------------------------
// rel+mask GEMM: g_logits[ng][wpos][pix] = valid ? rel + brel : -1e8
//   rel[wpos][pix] = sum_c Wrel[g][wpos][c] * qproj[ng][c][pix]
// Tile 64 wpos x 128 pix. grid (8 pixtile, 4 wpostile, 8 ng).
// ---------------------------------------------------------------------------
__global__ void __launch_bounds__(256) rel_kernel(
        const float* __restrict__ Wrel, const float* __restrict__ brel) {
    __shared__ float w_s[32 * 68];    // [kk][wpos]
    __shared__ float x_s[32 * 128];   // [kk][pix]

    const int pix0 = blockIdx.x * 128;
    const int d0   = blockIdx.y * 64;
    const int ng   = blockIdx.z;
    const int g    = ng & 1;
    const int tid  = threadIdx.x;

    const float* Wg = Wrel + g * 225 * 128;
    const float* X  = g_qproj + ng * 128 * 1024;

    const int td = tid >> 4;
    const int tm = tid & 15;

    u64 acc[4][4];
    #pragma unroll
    for (int dd = 0; dd < 4; dd++)
        #pragma unroll
        for (int mq = 0; mq < 4; mq++) acc[dd][mq] = 0ull;

    const int ldq = tid >> 3;
    const int lc4 = tid & 7;
    const int lk  = tid >> 5;
    const int lm4 = tid & 31;

    for (int kb = 0; kb < 4; kb++) {
        const int k0 = kb * 32;
        {
            float4 z = make_float4(0.f, 0.f, 0.f, 0.f);
            float4 fa = (d0 + ldq < 225)
                ? *(const float4*)(Wg + (d0 + ldq) * 128 + k0 + lc4 * 4) : z;
            float4 fb = (d0 + ldq + 32 < 225)
                ? *(const float4*)(Wg + (d0 + ldq + 32) * 128 + k0 + lc4 * 4) : z;
            w_s[(lc4 * 4 + 0) * 68 + ldq] = fa.x;
            w_s[(lc4 * 4 + 1) * 68 + ldq] = fa.y;
            w_s[(lc4 * 4 + 2) * 68 + ldq] = fa.z;
            w_s[(lc4 * 4 + 3) * 68 + ldq] = fa.w;
            w_s[(lc4 * 4 + 0) * 68 + ldq + 32] = fb.x;
            w_s[(lc4 * 4 + 1) * 68 + ldq + 32] = fb.y;
            w_s[(lc4 * 4 + 2) * 68 + ldq + 32] = fb.z;
            w_s[(lc4 * 4 + 3) * 68 + ldq + 32] = fb.w;
        }
        #pragma unroll
        for (int r = 0; r < 4; r++) {
            *(float4*)(x_s + (lk + 8 * r) * 128 + lm4 * 4) =
                *(const float4*)(X + (k0 + lk + 8 * r) * 1024 + pix0 + lm4 * 4);
        }
        __syncthreads();

        #pragma unroll 8
        for (int kk = 0; kk < 32; kk++) {
            float4 wv = *(const float4*)(w_s + kk * 68 + td * 4);
            u64 xv[4];
            #pragma unroll
            for (int mq = 0; mq < 4; mq++)
                xv[mq] = *(const u64*)(x_s + kk * 128 + 2 * tm + 32 * mq);
            u64 w0 = pack2(wv.x, wv.x), w1 = pack2(wv.y, wv.y);
            u64 w2 = pack2(wv.z, wv.z), w3 = pack2(wv.w, wv.w);
            #pragma unroll
            for (int mq = 0; mq < 4; mq++) {
                acc[0][mq] = fma2(w0, xv[mq], acc[0][mq]);
                acc[1][mq] = fma2(w1, xv[mq], acc[1][mq]);
                acc[2][mq] = fma2(w2, xv[mq], acc[2][mq]);
                acc[3][mq] = fma2(w3, xv[mq], acc[3][mq]);
            }
        }
        __syncthreads();
    }

    float* Lb = g_logits + ng * 230400;
    #pragma unroll
    for (int dd = 0; dd < 4; dd++) {
        const int wpos = d0 + td * 4 + dd;
        if (wpos >= 225) continue;
        const float bv = brel[g * 225 + wpos];
        const int dy = wpos / 15;
        const int dxw = wpos - dy * 15;
        #pragma unroll
        for (int mq = 0; mq < 4; mq++) {
            const int pix = pix0 + 2 * tm + 32 * mq;
            const int y = pix >> 5, x = pix & 31;
            const int iy = y + dy - 7;
            const bool ry = (iy >= 0) && (iy < 32);
            const int ix0 = x + dxw - 7;
            float2 t = unpack2(acc[dd][mq]);
            float v0 = (ry && ix0 >= 0 && ix0 < 32) ? t.x + bv : -1e8f;
            float v1 = (ry && ix0 + 1 >= 0 && ix0 + 1 < 32) ? t.y + bv : -1e8f;
            *(float2*)(Lb + wpos * 1024 + pix) = make_float2(v0, v1);
        }
    }
}

// ---------------------------------------------------------------------------
// QK-add kernel: adds q.k/T dot products into g_logits.
// Block = (ypair, dyhalf, ng). Loops over image rows R; row R serves
// (y0, dyA=R-y0+7) and (y1, dyA-1). 8 warps x 2 dx, lane = x.
// ---------------------------------------------------------------------------
constexpr int QK_Q0   = 0;
constexpr int QK_Q1   = 32 * 130;
constexpr int QK_SLAB = 2 * 32 * 130;
constexpr int QK_SMEM_FLOATS = QK_SLAB + 47 * 130;
constexpr int QK_SMEM_BYTES  = QK_SMEM_FLOATS * 4;   // 58 KB

__global__ void __launch_bounds__(256) qk_kernel() {
    extern __shared__ float sm[];
    float* q0s  = sm + QK_Q0;
    float* q1s  = sm + QK_Q1;
    float* slab = sm + QK_SLAB;

    const int yp = blockIdx.x;
    const int y0 = yp * 2, y1 = y0 + 1;
    const int h  = blockIdx.y;
    const int d0 = h ? 8 : 0;
    const int d1 = h ? 15 : 8;
    const int ng = blockIdx.z;
    const int tid = threadIdx.x;
    const int x = tid & 31, w = tid >> 5;
    const float invT = 0.08838834764831845f;

    const float* qb = g_qproj + ng * 131072;
    const float* kb = g_kproj + ng * 131072;
    float* Lb = g_logits + ng * 230400;

    // q rows y0, y1 transposed to [x][c]
    for (int i = tid; i < 4096; i += 256) {
        int c = i >> 5, xx = i & 31;
        q0s[xx * 130 + c] = qb[c * 1024 + y0 * 32 + xx];
        q1s[xx * 130 + c] = qb[c * 1024 + y1 * 32 + xx];
    }
    // zero permanent slab edges (px 0..6 and 39..45)
    for (int i = tid; i < 14 * 128; i += 256) {
        int e = i >> 7, c = i & 127;
        int px = (e < 7) ? e : e + 32;
        slab[px * 130 + c] = 0.f;
    }

    const int dx0 = w;
    const int dx1 = (w < 7) ? w + 8 : 0;

    const int Rlo = y0 + d0 - 7;
    const int Rhi = y0 + d1 - 7;     // inclusive

    for (int R = Rlo; R <= Rhi; R++) {
        if (R < 0 || R > 31) continue;            // uniform across block
        __syncthreads();                          // previous slab consumed
        for (int i = tid; i < 4096; i += 256) {
            int c = i >> 5, ix = i & 31;
            slab[(ix + 7) * 130 + c] = kb[c * 1024 + R * 32 + ix] * invT;
        }
        __syncthreads();

        u64 a00 = 0, a01 = 0, a10 = 0, a11 = 0;
        const float* qp0 = q0s + x * 130;
        const float* qp1 = q1s + x * 130;
        const float* k0p = slab + (x + dx0) * 130;
        const float* k1p = slab + (x + dx1) * 130;
        #pragma unroll 16
        for (int c2 = 0; c2 < 64; c2++) {
            u64 k0v = *(const u64*)(k0p + 2 * c2);
            u64 k1v = *(const u64*)(k1p + 2 * c2);
            u64 q0v = *(const u64*)(qp0 + 2 * c2);
            u64 q1v = *(const u64*)(qp1 + 2 * c2);
            a00 = fma2(q0v, k0v, a00);
            a01 = fma2(q0v, k1v, a01);
            a10 = fma2(q1v, k0v, a10);
            a11 = fma2(q1v, k1v, a11);
        }

        const int dyA = R - y0 + 7;
        const int dyB = dyA - 1;
        if (dyA >= d0 && dyA < d1) {
            float2 t = unpack2(a00);
            float* p = Lb + (dyA * 15 + dx0) * 1024 + y0 * 32 + x;
            *p += t.x + t.y;
            if (w < 7) {
                float2 u = unpack2(a01);
                float* p2 = Lb + (dyA * 15 + dx1) * 1024 + y0 * 32 + x;
                *p2 += u.x + u.y;
            }
        }
        if (dyB >= d0 && dyB < d1) {
            float2 t = unpack2(a10);
            float* p = Lb + (dyB * 15 + dx0) * 1024 + y1 * 32 + x;
            *p += t.x + t.y;
            if (w < 7) {
                float2 u = unpack2(a11);
                float* p2 = Lb + (dyB * 15 + dx1) * 1024 + y1 * 32 + x;
                *p2 += u.x + u.y;
            }
        }
    }
}

// ---------------------------------------------------------------------------
// softmax + aggregation kernel: one block per (y, g, n).
// ---------------------------------------------------------------------------
constexpr int AG_KV  = 0;                    // [px][c] stride 130, 46 rows
constexpr int AG_AUX = 46 * 130;             // vbias [dx][c] stride 132
constexpr int AG_QK  = AG_AUX + 15 * 132;    // [wpos][x]
constexpr int AG_RED = AG_QK + 225 * 32;
constexpr int AG_SMEM_FLOATS = AG_RED + 256;
constexpr int AG_SMEM_BYTES  = AG_SMEM_FLOATS * 4;   // ~62 KB

__global__ void __launch_bounds__(256) agg_kernel(const float* __restrict__ Vbias) {
    extern __shared__ float sm[];
    float* kv_s  = sm + AG_KV;
    float* aux   = sm + AG_AUX;
    float* qk_s  = sm + AG_QK;
    float* red_s = sm + AG_RED;

    const int y = blockIdx.x, g = blockIdx.y, n = blockIdx.z;
    const int ng = n * 2 + g;
    const int tid = threadIdx.x;
    const int x = tid & 31, w = tid >> 5;

    const float* vbp = g_vproj + ng * 131072;
    const float* vbg = Vbias + g * 28800;
    const float* Lb  = g_logits + ng * 230400;

    // load logits [225][32]
    for (int i = tid; i < 7200; i += 256)
        qk_s[i] = Lb[(i >> 5) * 1024 + y * 32 + (i & 31)];
    // zero permanent edges of v slab
    for (int i = tid; i < 14 * 128; i += 256) {
        int e = i >> 7, c = i & 127;
        int px = (e < 7) ? e : e + 32;
        kv_s[px * 130 + c] = 0.f;
    }
    __syncthreads();

    // ---------------- softmax over 225 positions ----------------
    {
        float lm = -1e30f;
        for (int ww = w; ww < 225; ww += 8) lm = fmaxf(lm, qk_s[ww * 32 + x]);
        red_s[w * 32 + x] = lm;
        __syncthreads();
        float m = red_s[x];
        #pragma unroll
        for (int i = 1; i < 8; i++) m = fmaxf(m, red_s[i * 32 + x]);
        __syncthreads();
        float ls = 0.f;
        for (int ww = w; ww < 225; ww += 8) {
            float e = __expf(qk_s[ww * 32 + x] - m);
            qk_s[ww * 32 + x] = e;
            ls += e;
        }
        red_s[w * 32 + x] = ls;
        __syncthreads();
        float s = red_s[x];
        #pragma unroll
        for (int i = 1; i < 8; i++) s += red_s[i * 32 + x];
        float rinv = 1.f / s;
        for (int ww = w; ww < 225; ww += 8) qk_s[ww * 32 + x] *= rinv;
    }

    // ---------------- aggregation ----------------
    u64 acc[8];
    #pragma unroll
    for (int j = 0; j < 8; j++) acc[j] = 0;
    const int cbase = w * 16;

    for (int dy = 0; dy < 15; dy++) {
        const int iy = y + dy - 7;
        const bool rv = (iy >= 0) && (iy < 32);
        __syncthreads();
        for (int i = tid; i < 4096; i += 256) {
            int c = i >> 5, ix = i & 31;
            kv_s[(ix + 7) * 130 + c] = rv ? vbp[c * 1024 + iy * 32 + ix] : 0.f;
        }
        for (int i = tid; i < 1920; i += 256) {
            int c = i / 15, dxx = i % 15;
            aux[dxx * 132 + c] = __ldg(vbg + c * 225 + dy * 15 + dxx);
        }
        __syncthreads();

        #pragma unroll 5
        for (int dx = 0; dx < 15; dx++) {
            float aw = qk_s[(dy * 15 + dx) * 32 + x];
            u64 aw2 = pack2(aw, aw);
            const float* vp = kv_s + (x + dx) * 130 + cbase;
            const float* bp = aux + dx * 132 + cbase;
            #pragma unroll
            for (int j = 0; j < 8; j++)
                acc[j] = fma2(aw2,
                              add2(*(const u64*)(vp + 2 * j), *(const u64*)(bp + 2 * j)),
                              acc[j]);
        }
    }

    float* ap = g_agg + ((y * 32 + x) * 4 + n) * 256 + g * 128 + cbase;
    #pragma unroll
    for (int j = 0; j < 8; j++) *(float2*)(ap + 2 * j) = unpack2(acc[j]);
}

// ---------------------------------------------------------------------------
// Output FC
// ---------------------------------------------------------------------------
__global__ void __launch_bounds__(256) fc_kernel(
        const float* __restrict__ Wfc, const float* __restrict__ bfc,
        float* __restrict__ out) {
    __shared__ float w_s[32 * 68];
    __shared__ float x_s[32 * 128];

    const int r0 = blockIdx.x * 64;
    const int d0 = blockIdx.y * 128;
    const int tid = threadIdx.x;
    const int td = tid >> 4;
    const int tm = tid & 15;

    u64 acc[4][4];
    #pragma unroll
    for (int mq = 0; mq < 4; mq++) {
        int d = d0 + 2 * tm + 32 * mq;
        u64 bb = pack2(bfc[d], bfc[d + 1]);
        #pragma unroll
        for (int rr = 0; rr < 4; rr++) acc[rr][mq] = bb;
    }

    const int lrq = tid >> 3;
    const int lc4 = tid & 7;
    const int ld  = tid & 127;
    const int lch = tid >> 7;

    for (int kb = 0; kb < 8; kb++) {
        const int k0 = kb * 32;
        {
            float4 fa = *(const float4*)(g_agg + (r0 + lrq) * 256 + k0 + lc4 * 4);
            float4 fb = *(const float4*)(g_agg + (r0 + lrq + 32) * 256 + k0 + lc4 * 4);
            w_s[(lc4 * 4 + 0) * 68 + lrq] = fa.x;
            w_s[(lc4 * 4 + 1) * 68 + lrq] = fa.y;
            w_s[(lc4 * 4 + 2) * 68 + lrq] = fa.z;
            w_s[(lc4 * 4 + 3) * 68 + lrq] = fa.w;
            w_s[(lc4 * 4 + 0) * 68 + lrq + 32] = fb.x;
            w_s[(lc4 * 4 + 1) * 68 + lrq + 32] = fb.y;
            w_s[(lc4 * 4 + 2) * 68 + lrq + 32] = fb.z;
            w_s[(lc4 * 4 + 3) * 68 + lrq + 32] = fb.w;
        }
        #pragma unroll
        for (int i = 0; i < 4; i++) {
            int cq = lch * 4 + i;
            float4 f = *(const float4*)(Wfc + (d0 + ld) * 256 + k0 + cq * 4);
            x_s[(cq * 4 + 0) * 128 + ld] = f.x;
            x_s[(cq * 4 + 1) * 128 + ld] = f.y;
            x_s[(cq * 4 + 2) * 128 + ld] = f.z;
            x_s[(cq * 4 + 3) * 128 + ld] = f.w;
        }
        __syncthreads();

        #pragma unroll 8
        for (int kk = 0; kk < 32; kk++) {
            float4 wv = *(const float4*)(w_s + kk * 68 + td * 4);
            u64 xv[4];
            #pragma unroll
            for (int mq = 0; mq < 4; mq++)
                xv[mq] = *(const u64*)(x_s + kk * 128 + 2 * tm + 32 * mq);
            u64 w0 = pack2(wv.x, wv.x), w1 = pack2(wv.y, wv.y);
            u64 w2 = pack2(wv.z, wv.z), w3 = pack2(wv.w, wv.w);
            #pragma unroll
            for (int mq = 0; mq < 4; mq++) {
                acc[0][mq] = fma2(w0, xv[mq], acc[0][mq]);
                acc[1][mq] = fma2(w1, xv[mq], acc[1][mq]);
                acc[2][mq] = fma2(w2, xv[mq], acc[2][mq]);
                acc[3][mq] = fma2(w3, xv[mq], acc[3][mq]);
            }
        }
        __syncthreads();
    }

    #pragma unroll
    for (int rr = 0; rr < 4; rr++) {
        float* op = out + (r0 + td * 4 + rr) * 256 + d0 + 2 * tm;
        #pragma unroll
        for (int mq = 0; mq < 4; mq++)
            *(float2*)(op + 32 * mq) = unpack2(acc[rr][mq]);
    }
}

// ---------------------------------------------------------------------------
extern "C" void kernel_launch(void* const* d_in, const int* in_sizes, int n_in,
                              void* d_out, int out_size) {
    const float* q    = (const float*)d_in[0];
    const float* k    = (const float*)d_in[1];
    const float* v    = (const float*)d_in[2];
    const float* Wq   = (const float*)d_in[3];
    const float* bq   = (const float*)d_in[4];
    const float* Wk   = (const float*)d_in[5];
    const float* bk   = (const float*)d_in[6];
    const float* Wv   = (const float*)d_in[7];
    const float* bv   = (const float*)d_in[8];
    const float* Wrel = (const float*)d_in[9];
    const float* brel = (const float*)d_in[10];
    const float* Vb   = (const float*)d_in[11];
    const float* Wfc  = (const float*)d_in[12];
    const float* bfc  = (const float*)d_in[13];
    float* out = (float*)d_out;

    cudaFuncSetAttribute(qk_kernel, cudaFuncAttributeMaxDynamicSharedMemorySize,
                         QK_SMEM_BYTES);
    cudaFuncSetAttribute(agg_kernel, cudaFuncAttributeMaxDynamicSharedMemorySize,
                         AG_SMEM_BYTES);

    dim3 pg(32, 4, 3);
    proj_kernel<<<pg, 256>>>(q, k, v, Wq, bq, Wk, bk, Wv, bv);

    dim3 rg(8, 4, 8);
    rel_kernel<<<rg, 256>>>(Wrel, brel);

    dim3 qg(16, 2, 8);
    qk_kernel<<<qg, 256, QK_SMEM_BYTES>>>();

    dim3 ag(32, 2, 4);
    agg_kernel<<<ag, 256, AG_SMEM_BYTES>>>(Vb);

    dim3 fg(64, 2);
    fc_kernel<<<fg, 256>>>(Wfc, bfc, out);
}